// round 2
// baseline (speedup 1.0000x reference)
#include <cuda_runtime.h>
#include <cstdint>

// out[e, 0:128]   = X[src[e], :]
// out[e, 128:256] = X[dst[e], :]
// X: [N, 128] fp32 (row = 512 B = 32 float4)
// indices: [E, 2] int32  (JAX x64 disabled -> int64 request yields int32)
// out: [E, 256] fp32 (row = 64 float4)
//
// One float4 per thread. Warp lanes (32) cover one full 512B source row,
// so the index load is warp-uniform and the gather read is 4x128B coalesced.

__global__ void __launch_bounds__(256) link_embed_gather_kernel(
    const float4* __restrict__ X,
    const int* __restrict__ idx,
    float4* __restrict__ out,
    int total_chunks)   // E * 64
{
    int t = blockIdx.x * blockDim.x + threadIdx.x;
    if (t >= total_chunks) return;

    int e = t >> 6;          // edge id
    int j = t & 63;          // float4 slot within output row (0..63)
    int half = j >> 5;       // 0 = src half, 1 = dst half
    int c = j & 31;          // float4 column within source row (0..31)

    int node = __ldg(&idx[e * 2 + half]);   // warp-uniform

    out[t] = __ldg(&X[(long long)node * 32 + c]);
}

extern "C" void kernel_launch(void* const* d_in, const int* in_sizes, int n_in,
                              void* d_out, int out_size)
{
    const float4* X = (const float4*)d_in[0];
    const int* idx = (const int*)d_in[1];
    float4* out = (float4*)d_out;

    int E = in_sizes[1] / 2;          // indices has E*2 int32 elements
    int total_chunks = E * 64;        // one float4 per thread

    int threads = 256;
    int blocks = (total_chunks + threads - 1) / threads;
    link_embed_gather_kernel<<<blocks, threads>>>(X, idx, out, total_chunks);
}

// round 3
// speedup vs baseline: 1.2930x; 1.2930x over previous
#include <cuda_runtime.h>
#include <cstdint>

// out[e, 0:128]   = X[src[e], :]
// out[e, 128:256] = X[dst[e], :]
// X: [N, 128] fp32 (row = 512 B = 32 float4)
// indices: [E, 2] int32
// out: [E, 256] fp32 (row = 64 float4)
//
// 4 independent float4 chunks per thread (grid-stride slices), so each warp
// keeps ~8 loads in flight instead of 1-2. Within each slice a warp's 32
// lanes cover exactly one 512B source row: warp-uniform index load +
// 4x128B coalesced gather. Stores use evict-first (.cs) so the 328MB output
// stream doesn't evict the 51MB X table from L2.

#define CHUNKS_PER_THREAD 4

__global__ void __launch_bounds__(256) link_embed_gather_kernel(
    const float4* __restrict__ X,
    const int* __restrict__ idx,
    float4* __restrict__ out,
    int total_chunks)   // E * 64
{
    const int stride = gridDim.x * blockDim.x;
    const int t0 = blockIdx.x * blockDim.x + threadIdx.x;

    int t[CHUNKS_PER_THREAD];
    int node[CHUNKS_PER_THREAD];
    bool valid[CHUNKS_PER_THREAD];

    // Phase 1: batch all index loads (independent, warp-uniform each)
    #pragma unroll
    for (int i = 0; i < CHUNKS_PER_THREAD; i++) {
        t[i] = t0 + i * stride;
        valid[i] = (t[i] < total_chunks);
        int e = t[i] >> 6;
        int half = (t[i] >> 5) & 1;
        node[i] = valid[i] ? __ldg(&idx[e * 2 + half]) : 0;
    }

    // Phase 2: batch all gathers (independent)
    float4 v[CHUNKS_PER_THREAD];
    #pragma unroll
    for (int i = 0; i < CHUNKS_PER_THREAD; i++) {
        int c = t[i] & 31;
        if (valid[i])
            v[i] = __ldg(&X[(long long)node[i] * 32 + c]);
    }

    // Phase 3: streaming stores (evict-first in L2)
    #pragma unroll
    for (int i = 0; i < CHUNKS_PER_THREAD; i++) {
        if (valid[i])
            __stcs(&out[t[i]], v[i]);
    }
}

extern "C" void kernel_launch(void* const* d_in, const int* in_sizes, int n_in,
                              void* d_out, int out_size)
{
    const float4* X = (const float4*)d_in[0];
    const int* idx = (const int*)d_in[1];
    float4* out = (float4*)d_out;

    int E = in_sizes[1] / 2;          // indices has E*2 int32 elements
    int total_chunks = E * 64;        // one float4 per chunk

    int threads = 256;
    int chunks_per_block = threads * CHUNKS_PER_THREAD;
    int blocks = (total_chunks + chunks_per_block - 1) / chunks_per_block;
    link_embed_gather_kernel<<<blocks, threads>>>(X, idx, out, total_chunks);
}

// round 4
// speedup vs baseline: 1.5040x; 1.1631x over previous
#include <cuda_runtime.h>
#include <cstdint>

// out[e, 0:128]   = X[src[e], :]
// out[e, 128:256] = X[dst[e], :]
// X: [N, 128] fp32 (row = 512 B = 32 float4)
// indices: [E, 2] int32
// out: [E, 256] fp32 (row = 64 float4)
//
// 8 independent float4 chunks per thread (grid-stride slices) -> ~8 gathers
// in flight per thread to cover DRAM/L2 latency. Warp lanes cover one 512B
// source row per slice: warp-uniform index load + 4x128B coalesced gather.
// Evict-first (.cs) stores keep the 328MB output stream from evicting the
// 51MB X table out of L2. Fast path is fully unpredicated (total_chunks is
// an exact multiple of block*CPT at this shape).

#define CPT 8

__global__ void __launch_bounds__(256) link_embed_gather_kernel(
    const float4* __restrict__ X,
    const int* __restrict__ idx,
    float4* __restrict__ out,
    int total_chunks)   // E * 64
{
    const int stride = gridDim.x * blockDim.x;
    const int t0 = blockIdx.x * blockDim.x + threadIdx.x;

    if (t0 + (CPT - 1) * stride < total_chunks) {
        // ---- fast path: no bounds checks ----
        int node[CPT];
        #pragma unroll
        for (int i = 0; i < CPT; i++) {
            int t = t0 + i * stride;
            int e = t >> 6;
            int half = (t >> 5) & 1;
            node[i] = __ldg(&idx[e * 2 + half]);   // warp-uniform
        }

        float4 v[CPT];
        #pragma unroll
        for (int i = 0; i < CPT; i++) {
            int t = t0 + i * stride;
            int c = t & 31;
            v[i] = __ldg(&X[(long long)node[i] * 32 + c]);
        }

        #pragma unroll
        for (int i = 0; i < CPT; i++) {
            __stcs(&out[t0 + i * stride], v[i]);
        }
    } else {
        // ---- guarded tail (never taken at the bench shape) ----
        #pragma unroll
        for (int i = 0; i < CPT; i++) {
            int t = t0 + i * stride;
            if (t < total_chunks) {
                int e = t >> 6;
                int half = (t >> 5) & 1;
                int c = t & 31;
                int node = __ldg(&idx[e * 2 + half]);
                __stcs(&out[t], __ldg(&X[(long long)node * 32 + c]));
            }
        }
    }
}

extern "C" void kernel_launch(void* const* d_in, const int* in_sizes, int n_in,
                              void* d_out, int out_size)
{
    const float4* X = (const float4*)d_in[0];
    const int* idx = (const int*)d_in[1];
    float4* out = (float4*)d_out;

    int E = in_sizes[1] / 2;          // indices has E*2 int32 elements
    int total_chunks = E * 64;        // one float4 per chunk

    int threads = 256;
    int chunks_per_block = threads * CPT;
    int blocks = (total_chunks + chunks_per_block - 1) / chunks_per_block;
    link_embed_gather_kernel<<<blocks, threads>>>(X, idx, out, total_chunks);
}